// round 7
// baseline (speedup 1.0000x reference)
#include <cuda_runtime.h>
#include <cuda_bf16.h>
#include <float.h>
#include <math.h>

// Problem constants
#define BB 8
#define NN 4096
#define CC 64
#define KK 30
#define E_TOT (BB*NN*KK)          // 983040
#define NBLK (E_TOT/256)          // 3840
#define ROWS_PER_BLOCK 16

// ---------------- scratch (device globals; no runtime allocation) ----------------
__device__ int   g_idx[E_TOT];                 // neighbor indices [B,N,K]
__device__ float g_h1[6*(size_t)E_TOT];        // layer1 pre-activations, SoA
__device__ float g_a2[3*(size_t)E_TOT];        // layer2 pre-activations, SoA
__device__ float g_a3[E_TOT];                  // layer3 pre-activations
__device__ float g_xT[(size_t)BB*NN*CC];       // x transposed to [B,N,C]
__device__ float g_part1[NBLK*12];
__device__ float g_part2[NBLK*6];
__device__ float g_part3[NBLK*2];
__device__ float g_bn[20];  // [0:6) sc1 [6:12) sh1 [12:15) sc2 [15:18) sh2 [18] sc3 [19] sh3

// ---------------- helpers ----------------
// Fused (sum, sumsq) block reduction: one pair of barriers per channel instead of two.
__device__ __forceinline__ float2 blockReduceSum2(float a, float b, float2* sh) {
    #pragma unroll
    for (int o = 16; o; o >>= 1) {
        a += __shfl_down_sync(0xffffffffu, a, o);
        b += __shfl_down_sync(0xffffffffu, b, o);
    }
    int w = threadIdx.x >> 5;
    if ((threadIdx.x & 31) == 0) sh[w] = make_float2(a, b);
    __syncthreads();
    float2 r = make_float2(0.f, 0.f);
    if (w == 0) {
        if (threadIdx.x < 8) r = sh[threadIdx.x];
        #pragma unroll
        for (int o = 4; o; o >>= 1) {
            r.x += __shfl_down_sync(0xffffffffu, r.x, o);
            r.y += __shfl_down_sync(0xffffffffu, r.y, o);
        }
    }
    __syncthreads();
    return r;  // valid in thread 0
}

__device__ __forceinline__ float blockReduceSum(float v, float* sh) {
    #pragma unroll
    for (int o = 16; o; o >>= 1) v += __shfl_down_sync(0xffffffffu, v, o);
    int w = threadIdx.x >> 5;
    if ((threadIdx.x & 31) == 0) sh[w] = v;
    __syncthreads();
    float r = 0.f;
    if (w == 0) {
        r = (threadIdx.x < 8) ? sh[threadIdx.x] : 0.f;
        #pragma unroll
        for (int o = 4; o; o >>= 1) r += __shfl_down_sync(0xffffffffu, r, o);
    }
    __syncthreads();
    return r;  // valid in thread 0
}

__device__ __forceinline__ float lrelu(float x) { return x > 0.f ? x : 0.2f * x; }

// ---------------- transpose x: [B,C,N] -> [B,N,C] ----------------
__global__ void transpose_kernel(const float* __restrict__ x) {
    __shared__ float tile[32][33];
    int b = blockIdx.z;
    int c0 = blockIdx.y * 32, n0 = blockIdx.x * 32;
    const float* xb = x + (size_t)b * CC * NN;
    #pragma unroll
    for (int i = threadIdx.y; i < 32; i += 8)
        tile[i][threadIdx.x] = xb[(size_t)(c0 + i) * NN + n0 + threadIdx.x];
    __syncthreads();
    float* xt = g_xT + (size_t)b * NN * CC;
    #pragma unroll
    for (int i = threadIdx.y; i < 32; i += 8)
        xt[(size_t)(n0 + i) * CC + c0 + threadIdx.x] = tile[threadIdx.x][i];
}

// ---------------- kNN: block handles 16 rows of one batch ----------------
__global__ void knn_kernel(const float* __restrict__ xloc) {
    extern __shared__ float sm[];
    float* px   = sm;
    float* py   = sm + NN;
    float* pz   = sm + 2*NN;
    float* dist = sm + 3*NN;
    float* tmax = sm + 4*NN;
    int*   targ = (int*)(sm + 4*NN + 256);
    __shared__ int s_winner;

    int b = blockIdx.y, tid = threadIdx.x;
    const float* xb = xloc + (size_t)b * 3 * NN;
    for (int m = tid; m < NN; m += 256) {
        px[m] = xb[m]; py[m] = xb[NN + m]; pz[m] = xb[2*NN + m];
    }
    __syncthreads();

    for (int rr = 0; rr < ROWS_PER_BLOCK; rr++) {
        int n = blockIdx.x * ROWS_PER_BLOCK + rr;
        float cx = px[n], cy = py[n], cz = pz[n];
        float lmax = -FLT_MAX; int larg = 0;
        #pragma unroll
        for (int i = 0; i < 16; i++) {
            int m = tid + 256 * i;
            float dx = px[m] - cx, dy = py[m] - cy, dz = pz[m] - cz;
            float key = -fmaf(dz, dz, fmaf(dy, dy, dx * dx)); // -(dist^2)
            dist[m] = key;
            if (key > lmax) { lmax = key; larg = m; }  // ascending m scan: ties -> lowest m
        }
        __syncthreads();
        int outbase = (b * NN + n) * KK;
        for (int it = 0; it < KK; it++) {
            tmax[tid] = lmax; targ[tid] = larg;
            __syncthreads();
            if (tid < 32) {
                float v = tmax[tid]; int wt = tid;
                #pragma unroll
                for (int j = 1; j < 8; j++) {
                    float v2 = tmax[tid + 32 * j];
                    if (v2 > v) { v = v2; wt = tid + 32 * j; }
                }
                #pragma unroll
                for (int o = 16; o; o >>= 1) {
                    float ov = __shfl_down_sync(0xffffffffu, v, o);
                    int   ow = __shfl_down_sync(0xffffffffu, wt, o);
                    // strict >, or tie -> lower slot index (deterministic)
                    if (ov > v || (ov == v && ow < wt)) { v = ov; wt = ow; }
                }
                if (tid == 0) {
                    int cand = targ[wt];
                    g_idx[outbase + it] = cand;
                    dist[cand] = -FLT_MAX;
                    s_winner = wt;
                }
            }
            __syncthreads();
            if (tid == s_winner) {
                lmax = -FLT_MAX; larg = 0;
                #pragma unroll
                for (int i = 0; i < 16; i++) {
                    int m = tid + 256 * i;
                    float v = dist[m];
                    if (v > lmax) { lmax = v; larg = m; }
                }
            }
        }
        __syncthreads();
    }
}

// ---------------- F1: spherical features -> h1, moment partials ----------------
__global__ void f1_kernel(const float* __restrict__ xloc, const float* __restrict__ W1) {
    __shared__ float sW[36];
    __shared__ float2 red[8];
    int tid = threadIdx.x;
    if (tid < 36) sW[tid] = W1[tid];
    __syncthreads();

    int e = blockIdx.x * 256 + tid;
    int b = e / (NN * KK);
    int rem = e - b * (NN * KK);
    int n = rem / KK;
    int idx = g_idx[e];
    const float* xb = xloc + (size_t)b * 3 * NN;
    float cx = xb[n], cy = xb[NN + n], cz = xb[2*NN + n];
    float xr = xb[idx] - cx, yr = xb[NN + idx] - cy, zr = xb[2*NN + idx] - cz;

    float sxy2 = fmaf(yr, yr, xr * xr);
    float r2   = fmaf(zr, zr, sxy2);
    float rho  = sqrtf(fmaxf(r2, 1e-20f));
    float sxy  = sqrtf(fmaxf(sxy2, 1e-20f));
    bool deg_r = r2 < 1e-20f;
    bool deg_p = sxy2 < 1e-20f;
    float theta = atan2f(deg_r ? 0.f : zr, deg_r ? 1.f : sxy);
    float phi   = atan2f(deg_p ? 0.f : yr, deg_p ? 1.f : xr);
    float mean  = (rho + theta + phi) * (1.f / 3.f);
    float f[6] = { rho, theta, phi, rho - mean, theta - mean, phi - mean };

    float h[6];
    #pragma unroll
    for (int j = 0; j < 6; j++) {
        float a = 0.f;
        #pragma unroll
        for (int i = 0; i < 6; i++) a = fmaf(sW[j * 6 + i], f[i], a);
        h[j] = a;
        g_h1[(size_t)j * E_TOT + e] = a;
    }
    for (int j = 0; j < 6; j++) {
        float2 s = blockReduceSum2(h[j], h[j] * h[j], red);
        if (tid == 0) {
            g_part1[blockIdx.x * 12 + j]     = s.x;
            g_part1[blockIdx.x * 12 + 6 + j] = s.y;
        }
    }
}

// ---------------- deterministic partial reduction -> BN scale/shift ----------------
__global__ void reduce_stats_kernel(int layer, const float* __restrict__ gamma,
                                    const float* __restrict__ beta) {
    __shared__ float red[8];
    __shared__ float tot[12];
    int nch = (layer == 1) ? 6 : (layer == 2) ? 3 : 1;
    const float* part = (layer == 1) ? g_part1 : (layer == 2) ? g_part2 : g_part3;
    int stride = 2 * nch;
    for (int j = 0; j < stride; j++) {
        float s = 0.f;
        for (int i = threadIdx.x; i < NBLK; i += 256) s += part[i * stride + j];
        s = blockReduceSum(s, red);
        if (threadIdx.x == 0) tot[j] = s;
        __syncthreads();
    }
    int off = (layer == 1) ? 0 : (layer == 2) ? 12 : 18;
    if (threadIdx.x < nch) {
        float inv = 1.f / (float)E_TOT;
        float mu  = tot[threadIdx.x] * inv;
        float var = tot[nch + threadIdx.x] * inv - mu * mu;
        float sc  = gamma[threadIdx.x] * rsqrtf(var + 1e-5f);
        g_bn[off + threadIdx.x] = sc;
        g_bn[off + nch + threadIdx.x] = beta[threadIdx.x] - mu * sc;
    }
}

// ---------------- F2: bn1+lrelu -> a2 ----------------
__global__ void f2_kernel(const float* __restrict__ W2) {
    __shared__ float sW[18];
    __shared__ float sb[12];
    __shared__ float2 red[8];
    int tid = threadIdx.x;
    if (tid < 18) sW[tid] = W2[tid];
    if (tid < 12) sb[tid] = g_bn[tid];
    __syncthreads();
    int e = blockIdx.x * 256 + tid;
    float y[6];
    #pragma unroll
    for (int j = 0; j < 6; j++) {
        float h = g_h1[(size_t)j * E_TOT + e];
        y[j] = lrelu(fmaf(h, sb[j], sb[6 + j]));
    }
    float a[3];
    #pragma unroll
    for (int j = 0; j < 3; j++) {
        float s = 0.f;
        #pragma unroll
        for (int i = 0; i < 6; i++) s = fmaf(sW[j * 6 + i], y[i], s);
        a[j] = s;
        g_a2[(size_t)j * E_TOT + e] = s;
    }
    for (int j = 0; j < 3; j++) {
        float2 s = blockReduceSum2(a[j], a[j] * a[j], red);
        if (tid == 0) {
            g_part2[blockIdx.x * 6 + j]     = s.x;
            g_part2[blockIdx.x * 6 + 3 + j] = s.y;
        }
    }
}

// ---------------- F3: bn2+lrelu -> a3 ----------------
__global__ void f3_kernel(const float* __restrict__ W3) {
    __shared__ float sW[3];
    __shared__ float sb[6];
    __shared__ float2 red[8];
    int tid = threadIdx.x;
    if (tid < 3) sW[tid] = W3[tid];
    if (tid < 6) sb[tid] = g_bn[12 + tid];
    __syncthreads();
    int e = blockIdx.x * 256 + tid;
    float s = 0.f;
    #pragma unroll
    for (int j = 0; j < 3; j++) {
        float a = g_a2[(size_t)j * E_TOT + e];
        float y = lrelu(fmaf(a, sb[j], sb[3 + j]));
        s = fmaf(sW[j], y, s);
    }
    g_a3[e] = s;
    float2 t = blockReduceSum2(s, s * s, red);
    if (tid == 0) {
        g_part3[blockIdx.x * 2]     = t.x;
        g_part3[blockIdx.x * 2 + 1] = t.y;
    }
}

// ---------------- F4: bn3+lrelu -> softmax -> gather -> out ----------------
__global__ void f4_kernel(float* __restrict__ out) {
    int gw = (blockIdx.x * blockDim.x + threadIdx.x) >> 5;  // global warp = point id
    int lane = threadIdx.x & 31;
    int b = gw >> 12, n = gw & (NN - 1);
    int base = gw * KK;

    float sc = g_bn[18], sh = g_bn[19];
    float logit = -FLT_MAX;
    int nb = 0;
    if (lane < KK) {
        float a = g_a3[base + lane];
        logit = lrelu(fmaf(a, sc, sh));
        nb = g_idx[base + lane];
    }
    float mx = logit;
    #pragma unroll
    for (int o = 16; o; o >>= 1) mx = fmaxf(mx, __shfl_xor_sync(0xffffffffu, mx, o));
    float ex = (lane < KK) ? expf(logit - mx) : 0.f;
    float s = ex;
    #pragma unroll
    for (int o = 16; o; o >>= 1) s += __shfl_xor_sync(0xffffffffu, s, o);
    float att = ex / s;

    const float* xTb = g_xT + (size_t)b * NN * CC;
    float acc0 = 0.f, acc1 = 0.f;
    #pragma unroll
    for (int kk = 0; kk < KK; kk++) {
        int   t = __shfl_sync(0xffffffffu, nb, kk);
        float a = __shfl_sync(0xffffffffu, att, kk);
        float2 v = *(const float2*)(xTb + (size_t)t * CC + lane * 2);
        acc0 = fmaf(a, v.x, acc0);
        acc1 = fmaf(a, v.y, acc1);
    }
    float2 c = *(const float2*)(xTb + (size_t)n * CC + lane * 2);
    float* ob = out + (size_t)b * CC * NN;
    ob[(size_t)(2 * lane)     * NN + n] = c.x + acc0;
    ob[(size_t)(2 * lane + 1) * NN + n] = c.y + acc1;
}

// ---------------- launch ----------------
extern "C" void kernel_launch(void* const* d_in, const int* in_sizes, int n_in,
                              void* d_out, int out_size) {
    const float* x_loc = (const float*)d_in[0];
    const float* x     = (const float*)d_in[1];
    const float* W1    = (const float*)d_in[2];
    const float* g1    = (const float*)d_in[3];
    const float* b1    = (const float*)d_in[4];
    const float* W2    = (const float*)d_in[5];
    const float* g2    = (const float*)d_in[6];
    const float* b2    = (const float*)d_in[7];
    const float* W3    = (const float*)d_in[8];
    const float* g3    = (const float*)d_in[9];
    const float* b3    = (const float*)d_in[10];
    float* out = (float*)d_out;

    const int knn_smem = (4 * NN + 256) * 4 + 256 * 4;  // 67584 bytes
    cudaFuncSetAttribute(knn_kernel, cudaFuncAttributeMaxDynamicSharedMemorySize, knn_smem);

    transpose_kernel<<<dim3(NN / 32, CC / 32, BB), dim3(32, 8)>>>(x);
    knn_kernel<<<dim3(NN / ROWS_PER_BLOCK, BB), 256, knn_smem>>>(x_loc);
    f1_kernel<<<NBLK, 256>>>(x_loc, W1);
    reduce_stats_kernel<<<1, 256>>>(1, g1, b1);
    f2_kernel<<<NBLK, 256>>>(W2);
    reduce_stats_kernel<<<1, 256>>>(2, g2, b2);
    f3_kernel<<<NBLK, 256>>>(W3);
    reduce_stats_kernel<<<1, 256>>>(3, g3, b3);
    f4_kernel<<<(BB * NN) / 8, 256>>>(out);
}

// round 8
// speedup vs baseline: 3.1864x; 3.1864x over previous
#include <cuda_runtime.h>
#include <cuda_bf16.h>
#include <float.h>
#include <math.h>

// Problem constants
#define BB 8
#define NN 4096
#define CC 64
#define KK 30
#define E_TOT (BB*NN*KK)          // 983040
#define NBLK (E_TOT/256)          // 3840

// ---------------- scratch (device globals; no runtime allocation) ----------------
__device__ int   g_idx[E_TOT];                 // neighbor indices [B,N,K]
__device__ float g_h1[6*(size_t)E_TOT];        // layer1 pre-activations, SoA
__device__ float g_a2[3*(size_t)E_TOT];        // layer2 pre-activations, SoA
__device__ float g_a3[E_TOT];                  // layer3 pre-activations
__device__ float g_xT[(size_t)BB*NN*CC];       // x transposed to [B,N,C]
// partials stored transposed: [stat][block] for coalesced reduction
__device__ float g_part1[12*NBLK];
__device__ float g_part2[6*NBLK];
__device__ float g_part3[2*NBLK];
__device__ float g_bn[20];  // [0:6) sc1 [6:12) sh1 [12:15) sc2 [15:18) sh2 [18] sc3 [19] sh3

// ---------------- helpers ----------------
__device__ __forceinline__ float2 blockReduceSum2(float a, float b, float2* sh) {
    #pragma unroll
    for (int o = 16; o; o >>= 1) {
        a += __shfl_down_sync(0xffffffffu, a, o);
        b += __shfl_down_sync(0xffffffffu, b, o);
    }
    int w = threadIdx.x >> 5;
    if ((threadIdx.x & 31) == 0) sh[w] = make_float2(a, b);
    __syncthreads();
    float2 r = make_float2(0.f, 0.f);
    if (w == 0) {
        if (threadIdx.x < 8) r = sh[threadIdx.x];
        #pragma unroll
        for (int o = 4; o; o >>= 1) {
            r.x += __shfl_down_sync(0xffffffffu, r.x, o);
            r.y += __shfl_down_sync(0xffffffffu, r.y, o);
        }
    }
    __syncthreads();
    return r;  // valid in thread 0
}

__device__ __forceinline__ float lrelu(float x) { return x > 0.f ? x : 0.2f * x; }

// ---------------- transpose x: [B,C,N] -> [B,N,C] ----------------
__global__ void transpose_kernel(const float* __restrict__ x) {
    __shared__ float tile[32][33];
    int b = blockIdx.z;
    int c0 = blockIdx.y * 32, n0 = blockIdx.x * 32;
    const float* xb = x + (size_t)b * CC * NN;
    #pragma unroll
    for (int i = threadIdx.y; i < 32; i += 8)
        tile[i][threadIdx.x] = xb[(size_t)(c0 + i) * NN + n0 + threadIdx.x];
    __syncthreads();
    float* xt = g_xT + (size_t)b * NN * CC;
    #pragma unroll
    for (int i = threadIdx.y; i < 32; i += 8)
        xt[(size_t)(n0 + i) * CC + c0 + threadIdx.x] = tile[threadIdx.x][i];
}

// ---------------- kNN: one warp per query row, register 4-list selection ----------------
// Key = (float_bits(d2) << 32) | idx  — d2 >= 0 so float bits are order-monotone,
// idx in low bits makes keys unique => exact tie-break (lowest index) and exact
// exclusion on refill. Lane l owns candidates m = i*32 + l (coalesced).
__global__ void __launch_bounds__(256) knn_kernel(const float* __restrict__ xloc) {
    const unsigned FULL = 0xffffffffu;
    const unsigned long long KMAX = 0xFFFFFFFFFFFFFFFFull;
    int b = blockIdx.y;
    int warp = threadIdx.x >> 5, lane = threadIdx.x & 31;
    int n = blockIdx.x * 8 + warp;

    const float* px = xloc + (size_t)b * 3 * NN;
    const float* py = px + NN;
    const float* pz = px + 2 * NN;
    float cx = __ldg(px + n), cy = __ldg(py + n), cz = __ldg(pz + n);

    // sorted ascending 4-list in registers
    unsigned long long k0 = KMAX, k1 = KMAX, k2 = KMAX, k3 = KMAX;

    #pragma unroll 4
    for (int i = 0; i < 128; i++) {
        int m = i * 32 + lane;
        float dx = __ldg(px + m) - cx;
        float dy = __ldg(py + m) - cy;
        float dz = __ldg(pz + m) - cz;
        float d2 = fmaf(dz, dz, fmaf(dy, dy, dx * dx));
        unsigned long long key =
            ((unsigned long long)__float_as_uint(d2) << 32) | (unsigned)m;
        if (key < k3) {
            if (key < k2) {
                k3 = k2;
                if (key < k1) { k2 = k1; if (key < k0) { k1 = k0; k0 = key; } else k1 = key; }
                else k2 = key;
            } else k3 = key;
        }
    }

    unsigned long long lastpop = 0;
    int outbase = (b * NN + n) * KK;

    for (int it = 0; it < KK; it++) {
        // warp-wide u64 min of per-lane heads
        unsigned long long v = k0;
        #pragma unroll
        for (int o = 16; o; o >>= 1) {
            unsigned long long ov = __shfl_xor_sync(FULL, v, o);
            v = (ov < v) ? ov : v;
        }
        if (lane == 0) g_idx[outbase + it] = (int)(unsigned)(v & 0xFFFFFFFFull);
        // exactly one lane holds v (keys unique); it pops
        if (k0 == v) {
            lastpop = v;
            k0 = k1; k1 = k2; k2 = k3; k3 = KMAX;
            if (k0 == KMAX) {
                // refill: rescan my 128 candidates, keep 4 smallest keys > lastpop
                for (int i = 0; i < 128; i++) {
                    int m = i * 32 + lane;
                    float dx = __ldg(px + m) - cx;
                    float dy = __ldg(py + m) - cy;
                    float dz = __ldg(pz + m) - cz;
                    float d2 = fmaf(dz, dz, fmaf(dy, dy, dx * dx));
                    unsigned long long key =
                        ((unsigned long long)__float_as_uint(d2) << 32) | (unsigned)m;
                    if (key > lastpop && key < k3) {
                        if (key < k2) {
                            k3 = k2;
                            if (key < k1) { k2 = k1; if (key < k0) { k1 = k0; k0 = key; } else k1 = key; }
                            else k2 = key;
                        } else k3 = key;
                    }
                }
            }
        }
    }
}

// ---------------- F1: spherical features -> h1, moment partials ----------------
__global__ void f1_kernel(const float* __restrict__ xloc, const float* __restrict__ W1) {
    __shared__ float sW[36];
    __shared__ float2 red[8];
    int tid = threadIdx.x;
    if (tid < 36) sW[tid] = W1[tid];
    __syncthreads();

    int e = blockIdx.x * 256 + tid;
    int b = e / (NN * KK);
    int rem = e - b * (NN * KK);
    int n = rem / KK;
    int idx = g_idx[e];
    const float* xb = xloc + (size_t)b * 3 * NN;
    float cx = xb[n], cy = xb[NN + n], cz = xb[2*NN + n];
    float xr = xb[idx] - cx, yr = xb[NN + idx] - cy, zr = xb[2*NN + idx] - cz;

    float sxy2 = fmaf(yr, yr, xr * xr);
    float r2   = fmaf(zr, zr, sxy2);
    float rho  = sqrtf(fmaxf(r2, 1e-20f));
    float sxy  = sqrtf(fmaxf(sxy2, 1e-20f));
    bool deg_r = r2 < 1e-20f;
    bool deg_p = sxy2 < 1e-20f;
    float theta = atan2f(deg_r ? 0.f : zr, deg_r ? 1.f : sxy);
    float phi   = atan2f(deg_p ? 0.f : yr, deg_p ? 1.f : xr);
    float mean  = (rho + theta + phi) * (1.f / 3.f);
    float f[6] = { rho, theta, phi, rho - mean, theta - mean, phi - mean };

    float h[6];
    #pragma unroll
    for (int j = 0; j < 6; j++) {
        float a = 0.f;
        #pragma unroll
        for (int i = 0; i < 6; i++) a = fmaf(sW[j * 6 + i], f[i], a);
        h[j] = a;
        g_h1[(size_t)j * E_TOT + e] = a;
    }
    #pragma unroll
    for (int j = 0; j < 6; j++) {
        float2 s = blockReduceSum2(h[j], h[j] * h[j], red);
        if (tid == 0) {
            g_part1[j * NBLK + blockIdx.x]       = s.x;
            g_part1[(6 + j) * NBLK + blockIdx.x] = s.y;
        }
    }
}

// ---------------- deterministic partial reduction -> BN scale/shift ----------------
// one warp per statistic (coalesced over NBLK), 384 threads = 12 warps
__global__ void reduce_stats_kernel(int layer, const float* __restrict__ gamma,
                                    const float* __restrict__ beta) {
    __shared__ float tot[12];
    int nch = (layer == 1) ? 6 : (layer == 2) ? 3 : 1;
    const float* part = (layer == 1) ? g_part1 : (layer == 2) ? g_part2 : g_part3;
    int w = threadIdx.x >> 5, lane = threadIdx.x & 31;
    if (w < 2 * nch) {
        const float* p = part + (size_t)w * NBLK;
        float s = 0.f;
        for (int i = lane; i < NBLK; i += 32) s += p[i];
        #pragma unroll
        for (int o = 16; o; o >>= 1) s += __shfl_down_sync(0xffffffffu, s, o);
        if (lane == 0) tot[w] = s;
    }
    __syncthreads();
    int off = (layer == 1) ? 0 : (layer == 2) ? 12 : 18;
    if (threadIdx.x < nch) {
        float inv = 1.f / (float)E_TOT;
        float mu  = tot[threadIdx.x] * inv;
        float var = tot[nch + threadIdx.x] * inv - mu * mu;
        float sc  = gamma[threadIdx.x] * rsqrtf(var + 1e-5f);
        g_bn[off + threadIdx.x] = sc;
        g_bn[off + nch + threadIdx.x] = beta[threadIdx.x] - mu * sc;
    }
}

// ---------------- F2: bn1+lrelu -> a2 ----------------
__global__ void f2_kernel(const float* __restrict__ W2) {
    __shared__ float sW[18];
    __shared__ float sb[12];
    __shared__ float2 red[8];
    int tid = threadIdx.x;
    if (tid < 18) sW[tid] = W2[tid];
    if (tid < 12) sb[tid] = g_bn[tid];
    __syncthreads();
    int e = blockIdx.x * 256 + tid;
    float y[6];
    #pragma unroll
    for (int j = 0; j < 6; j++) {
        float h = g_h1[(size_t)j * E_TOT + e];
        y[j] = lrelu(fmaf(h, sb[j], sb[6 + j]));
    }
    float a[3];
    #pragma unroll
    for (int j = 0; j < 3; j++) {
        float s = 0.f;
        #pragma unroll
        for (int i = 0; i < 6; i++) s = fmaf(sW[j * 6 + i], y[i], s);
        a[j] = s;
        g_a2[(size_t)j * E_TOT + e] = s;
    }
    #pragma unroll
    for (int j = 0; j < 3; j++) {
        float2 s = blockReduceSum2(a[j], a[j] * a[j], red);
        if (tid == 0) {
            g_part2[j * NBLK + blockIdx.x]       = s.x;
            g_part2[(3 + j) * NBLK + blockIdx.x] = s.y;
        }
    }
}

// ---------------- F3: bn2+lrelu -> a3 ----------------
__global__ void f3_kernel(const float* __restrict__ W3) {
    __shared__ float sW[3];
    __shared__ float sb[6];
    __shared__ float2 red[8];
    int tid = threadIdx.x;
    if (tid < 3) sW[tid] = W3[tid];
    if (tid < 6) sb[tid] = g_bn[12 + tid];
    __syncthreads();
    int e = blockIdx.x * 256 + tid;
    float s = 0.f;
    #pragma unroll
    for (int j = 0; j < 3; j++) {
        float a = g_a2[(size_t)j * E_TOT + e];
        float y = lrelu(fmaf(a, sb[j], sb[3 + j]));
        s = fmaf(sW[j], y, s);
    }
    g_a3[e] = s;
    float2 t = blockReduceSum2(s, s * s, red);
    if (tid == 0) {
        g_part3[blockIdx.x]        = t.x;
        g_part3[NBLK + blockIdx.x] = t.y;
    }
}

// ---------------- F4: bn3+lrelu -> softmax -> gather -> out ----------------
__global__ void f4_kernel(float* __restrict__ out) {
    int gw = (blockIdx.x * blockDim.x + threadIdx.x) >> 5;  // global warp = point id
    int lane = threadIdx.x & 31;
    int b = gw >> 12, n = gw & (NN - 1);
    int base = gw * KK;

    float sc = g_bn[18], sh = g_bn[19];
    float logit = -FLT_MAX;
    int nb = 0;
    if (lane < KK) {
        float a = g_a3[base + lane];
        logit = lrelu(fmaf(a, sc, sh));
        nb = g_idx[base + lane];
    }
    float mx = logit;
    #pragma unroll
    for (int o = 16; o; o >>= 1) mx = fmaxf(mx, __shfl_xor_sync(0xffffffffu, mx, o));
    float ex = (lane < KK) ? expf(logit - mx) : 0.f;
    float s = ex;
    #pragma unroll
    for (int o = 16; o; o >>= 1) s += __shfl_xor_sync(0xffffffffu, s, o);
    float att = ex / s;

    const float* xTb = g_xT + (size_t)b * NN * CC;
    float acc0 = 0.f, acc1 = 0.f;
    #pragma unroll
    for (int kk = 0; kk < KK; kk++) {
        int   t = __shfl_sync(0xffffffffu, nb, kk);
        float a = __shfl_sync(0xffffffffu, att, kk);
        float2 v = *(const float2*)(xTb + (size_t)t * CC + lane * 2);
        acc0 = fmaf(a, v.x, acc0);
        acc1 = fmaf(a, v.y, acc1);
    }
    float2 c = *(const float2*)(xTb + (size_t)n * CC + lane * 2);
    float* ob = out + (size_t)b * CC * NN;
    ob[(size_t)(2 * lane)     * NN + n] = c.x + acc0;
    ob[(size_t)(2 * lane + 1) * NN + n] = c.y + acc1;
}

// ---------------- launch ----------------
extern "C" void kernel_launch(void* const* d_in, const int* in_sizes, int n_in,
                              void* d_out, int out_size) {
    const float* x_loc = (const float*)d_in[0];
    const float* x     = (const float*)d_in[1];
    const float* W1    = (const float*)d_in[2];
    const float* g1    = (const float*)d_in[3];
    const float* b1    = (const float*)d_in[4];
    const float* W2    = (const float*)d_in[5];
    const float* g2    = (const float*)d_in[6];
    const float* b2    = (const float*)d_in[7];
    const float* W3    = (const float*)d_in[8];
    const float* g3    = (const float*)d_in[9];
    const float* b3    = (const float*)d_in[10];
    float* out = (float*)d_out;

    transpose_kernel<<<dim3(NN / 32, CC / 32, BB), dim3(32, 8)>>>(x);
    knn_kernel<<<dim3(NN / 8, BB), 256>>>(x_loc);
    f1_kernel<<<NBLK, 256>>>(x_loc, W1);
    reduce_stats_kernel<<<1, 384>>>(1, g1, b1);
    f2_kernel<<<NBLK, 256>>>(W2);
    reduce_stats_kernel<<<1, 384>>>(2, g2, b2);
    f3_kernel<<<NBLK, 256>>>(W3);
    reduce_stats_kernel<<<1, 384>>>(3, g3, b3);
    f4_kernel<<<(BB * NN) / 8, 256>>>(out);
}

// round 10
// speedup vs baseline: 3.4315x; 1.0769x over previous
#include <cuda_runtime.h>
#include <cuda_bf16.h>
#include <float.h>
#include <math.h>

// Problem constants
#define BB 8
#define NN 4096
#define CC 64
#define KK 30
#define E_TOT (BB*NN*KK)          // 983040
#define EPB   2048                // elements per block in F kernels (256 thr x 8)
#define NBLK2 (E_TOT/EPB)         // 480

// ---------------- scratch (device globals; no runtime allocation) ----------------
__device__ int   g_idx[E_TOT];                 // neighbor indices [B,N,K]
__device__ float g_h1[6*(size_t)E_TOT];        // layer1 pre-activations, SoA
__device__ float g_a2[3*(size_t)E_TOT];        // layer2 pre-activations, SoA
__device__ float g_a3[E_TOT];                  // layer3 pre-activations
__device__ float g_xT[(size_t)BB*NN*CC];       // x transposed to [B,N,C]
// partials transposed: [stat][block]
__device__ float g_part1[12*NBLK2];
__device__ float g_part2[6*NBLK2];
__device__ float g_part3[2*NBLK2];
__device__ float g_bn[20];  // [0:6) sc1 [6:12) sh1 [12:15) sc2 [15:18) sh2 [18] sc3 [19] sh3
__device__ unsigned g_cnt1 = 0, g_cnt2 = 0, g_cnt3 = 0;

// ---------------- helpers ----------------
__device__ __forceinline__ float2 blockReduceSum2(float a, float b, float2* sh) {
    #pragma unroll
    for (int o = 16; o; o >>= 1) {
        a += __shfl_down_sync(0xffffffffu, a, o);
        b += __shfl_down_sync(0xffffffffu, b, o);
    }
    int w = threadIdx.x >> 5;
    if ((threadIdx.x & 31) == 0) sh[w] = make_float2(a, b);
    __syncthreads();
    float2 r = make_float2(0.f, 0.f);
    if (w == 0) {
        if (threadIdx.x < 8) r = sh[threadIdx.x];
        #pragma unroll
        for (int o = 4; o; o >>= 1) {
            r.x += __shfl_down_sync(0xffffffffu, r.x, o);
            r.y += __shfl_down_sync(0xffffffffu, r.y, o);
        }
    }
    __syncthreads();
    return r;  // valid in thread 0
}

__device__ __forceinline__ float lrelu(float x) { return x > 0.f ? x : 0.2f * x; }

// Last-block finalize: reduce `nstat` partial rows of length NBLK2 (fixed order,
// deterministic), compute BN scale/shift for `nch` channels into g_bn[off..].
__device__ __forceinline__ void finalize_bn(const float* part, int nstat, int nch, int off,
                                            const float* gamma, const float* beta,
                                            float* tot /* shared[12] */) {
    __threadfence();
    int w = threadIdx.x >> 5, lane = threadIdx.x & 31;
    for (int st = w; st < nstat; st += 8) {
        const float* p = part + (size_t)st * NBLK2;
        float s = 0.f;
        for (int i = lane; i < NBLK2; i += 32) s += p[i];
        #pragma unroll
        for (int o = 16; o; o >>= 1) s += __shfl_down_sync(0xffffffffu, s, o);
        if (lane == 0) tot[st] = s;
    }
    __syncthreads();
    if (threadIdx.x < nch) {
        float inv = 1.f / (float)E_TOT;
        float mu  = tot[threadIdx.x] * inv;
        float var = tot[nch + threadIdx.x] * inv - mu * mu;
        float sc  = gamma[threadIdx.x] * rsqrtf(var + 1e-5f);
        g_bn[off + threadIdx.x] = sc;
        g_bn[off + nch + threadIdx.x] = beta[threadIdx.x] - mu * sc;
    }
}

// ---------------- transpose x: [B,C,N] -> [B,N,C] ----------------
__global__ void transpose_kernel(const float* __restrict__ x) {
    __shared__ float tile[32][33];
    int b = blockIdx.z;
    int c0 = blockIdx.y * 32, n0 = blockIdx.x * 32;
    const float* xb = x + (size_t)b * CC * NN;
    #pragma unroll
    for (int i = threadIdx.y; i < 32; i += 8)
        tile[i][threadIdx.x] = xb[(size_t)(c0 + i) * NN + n0 + threadIdx.x];
    __syncthreads();
    float* xt = g_xT + (size_t)b * NN * CC;
    #pragma unroll
    for (int i = threadIdx.y; i < 32; i += 8)
        xt[(size_t)(n0 + i) * CC + c0 + threadIdx.x] = tile[threadIdx.x][i];
}

// ---------------- kNN: one warp per query row, register 4-list selection ----------------
// Key = (float_bits(d2) << 32) | idx  — d2 >= 0 so float bits are order-monotone,
// idx in low bits makes keys unique => exact tie-break (lowest index) and exact
// exclusion on refill. Lane l owns candidates m = 4*(i*32+l)+j via float4 loads.
__global__ void __launch_bounds__(256) knn_kernel(const float* __restrict__ xloc) {
    const unsigned FULL = 0xffffffffu;
    const unsigned long long KMAX = 0xFFFFFFFFFFFFFFFFull;
    int b = blockIdx.y;
    int warp = threadIdx.x >> 5, lane = threadIdx.x & 31;
    int n = blockIdx.x * 8 + warp;

    const float* px = xloc + (size_t)b * 3 * NN;
    const float* py = px + NN;
    const float* pz = px + 2 * NN;
    const float4* px4 = (const float4*)px;
    const float4* py4 = (const float4*)py;
    const float4* pz4 = (const float4*)pz;
    float cx = __ldg(px + n), cy = __ldg(py + n), cz = __ldg(pz + n);

    // sorted ascending 4-list in registers
    unsigned long long k0 = KMAX, k1 = KMAX, k2 = KMAX, k3 = KMAX;

    #pragma unroll 2
    for (int i = 0; i < 32; i++) {
        int base = i * 32 + lane;
        float4 X = __ldg(px4 + base);
        float4 Y = __ldg(py4 + base);
        float4 Z = __ldg(pz4 + base);
        #pragma unroll
        for (int j = 0; j < 4; j++) {
            float dx = ((const float*)&X)[j] - cx;
            float dy = ((const float*)&Y)[j] - cy;
            float dz = ((const float*)&Z)[j] - cz;
            float d2 = fmaf(dz, dz, fmaf(dy, dy, dx * dx));
            unsigned long long key =
                ((unsigned long long)__float_as_uint(d2) << 32) | (unsigned)(base * 4 + j);
            if (key < k3) {
                if (key < k2) {
                    k3 = k2;
                    if (key < k1) { k2 = k1; if (key < k0) { k1 = k0; k0 = key; } else k1 = key; }
                    else k2 = key;
                } else k3 = key;
            }
        }
    }

    unsigned long long lastpop = 0;
    int outbase = (b * NN + n) * KK;

    for (int it = 0; it < KK; it++) {
        // warp-wide u64 min of per-lane heads
        unsigned long long v = k0;
        #pragma unroll
        for (int o = 16; o; o >>= 1) {
            unsigned long long ov = __shfl_xor_sync(FULL, v, o);
            v = (ov < v) ? ov : v;
        }
        if (lane == 0) g_idx[outbase + it] = (int)(unsigned)(v & 0xFFFFFFFFull);
        // exactly one lane holds v (keys unique); it pops
        if (k0 == v) {
            lastpop = v;
            k0 = k1; k1 = k2; k2 = k3; k3 = KMAX;
            if (k0 == KMAX) {
                // refill: rescan my candidates, keep 4 smallest keys > lastpop
                for (int i = 0; i < 32; i++) {
                    int base = i * 32 + lane;
                    float4 X = __ldg(px4 + base);
                    float4 Y = __ldg(py4 + base);
                    float4 Z = __ldg(pz4 + base);
                    #pragma unroll
                    for (int j = 0; j < 4; j++) {
                        float dx = ((const float*)&X)[j] - cx;
                        float dy = ((const float*)&Y)[j] - cy;
                        float dz = ((const float*)&Z)[j] - cz;
                        float d2 = fmaf(dz, dz, fmaf(dy, dy, dx * dx));
                        unsigned long long key =
                            ((unsigned long long)__float_as_uint(d2) << 32) | (unsigned)(base * 4 + j);
                        if (key > lastpop && key < k3) {
                            if (key < k2) {
                                k3 = k2;
                                if (key < k1) { k2 = k1; if (key < k0) { k1 = k0; k0 = key; } else k1 = key; }
                                else k2 = key;
                            } else k3 = key;
                        }
                    }
                }
            }
        }
    }
}

// ---------------- F1: spherical features -> h1 + fused BN1 stats ----------------
__global__ void __launch_bounds__(256) f1_kernel(const float* __restrict__ xloc,
                                                 const float* __restrict__ W1,
                                                 const float* __restrict__ g1,
                                                 const float* __restrict__ b1) {
    __shared__ float sW[36];
    __shared__ float2 red[8];
    __shared__ float tot[12];
    __shared__ bool s_last;
    int tid = threadIdx.x;
    if (tid < 36) sW[tid] = W1[tid];
    __syncthreads();

    float sum[6] = {0,0,0,0,0,0}, ssq[6] = {0,0,0,0,0,0};

    #pragma unroll
    for (int c = 0; c < 8; c++) {
        int e = blockIdx.x * EPB + c * 256 + tid;
        int b = e / (NN * KK);
        int rem = e - b * (NN * KK);
        int n = rem / KK;
        int idx = g_idx[e];
        const float* xb = xloc + (size_t)b * 3 * NN;
        float cx = xb[n], cy = xb[NN + n], cz = xb[2*NN + n];
        float xr = xb[idx] - cx, yr = xb[NN + idx] - cy, zr = xb[2*NN + idx] - cz;

        float sxy2 = fmaf(yr, yr, xr * xr);
        float r2   = fmaf(zr, zr, sxy2);
        float rho  = sqrtf(fmaxf(r2, 1e-20f));
        float sxy  = sqrtf(fmaxf(sxy2, 1e-20f));
        bool deg_r = r2 < 1e-20f;
        bool deg_p = sxy2 < 1e-20f;
        float theta = atan2f(deg_r ? 0.f : zr, deg_r ? 1.f : sxy);
        float phi   = atan2f(deg_p ? 0.f : yr, deg_p ? 1.f : xr);
        float mean  = (rho + theta + phi) * (1.f / 3.f);
        float f[6] = { rho, theta, phi, rho - mean, theta - mean, phi - mean };

        #pragma unroll
        for (int j = 0; j < 6; j++) {
            float a = 0.f;
            #pragma unroll
            for (int i = 0; i < 6; i++) a = fmaf(sW[j * 6 + i], f[i], a);
            g_h1[(size_t)j * E_TOT + e] = a;
            sum[j] += a;
            ssq[j] = fmaf(a, a, ssq[j]);
        }
    }

    #pragma unroll
    for (int j = 0; j < 6; j++) {
        float2 s = blockReduceSum2(sum[j], ssq[j], red);
        if (tid == 0) {
            g_part1[j * NBLK2 + blockIdx.x]       = s.x;
            g_part1[(6 + j) * NBLK2 + blockIdx.x] = s.y;
        }
    }
    if (tid == 0) {
        __threadfence();
        s_last = (atomicAdd(&g_cnt1, 1u) == NBLK2 - 1);
    }
    __syncthreads();
    if (s_last) {
        finalize_bn(g_part1, 12, 6, 0, g1, b1, tot);
        if (tid == 0) g_cnt1 = 0;
    }
}

// ---------------- F2: bn1+lrelu -> a2 + fused BN2 stats ----------------
__global__ void __launch_bounds__(256) f2_kernel(const float* __restrict__ W2,
                                                 const float* __restrict__ g2,
                                                 const float* __restrict__ b2) {
    __shared__ float sW[18];
    __shared__ float sb[12];
    __shared__ float2 red[8];
    __shared__ float tot[12];
    __shared__ bool s_last;
    int tid = threadIdx.x;
    if (tid < 18) sW[tid] = W2[tid];
    if (tid < 12) sb[tid] = g_bn[tid];
    __syncthreads();

    float sum[3] = {0,0,0}, ssq[3] = {0,0,0};

    #pragma unroll
    for (int c = 0; c < 8; c++) {
        int e = blockIdx.x * EPB + c * 256 + tid;
        float y[6];
        #pragma unroll
        for (int j = 0; j < 6; j++) {
            float h = g_h1[(size_t)j * E_TOT + e];
            y[j] = lrelu(fmaf(h, sb[j], sb[6 + j]));
        }
        #pragma unroll
        for (int j = 0; j < 3; j++) {
            float s = 0.f;
            #pragma unroll
            for (int i = 0; i < 6; i++) s = fmaf(sW[j * 6 + i], y[i], s);
            g_a2[(size_t)j * E_TOT + e] = s;
            sum[j] += s;
            ssq[j] = fmaf(s, s, ssq[j]);
        }
    }

    #pragma unroll
    for (int j = 0; j < 3; j++) {
        float2 s = blockReduceSum2(sum[j], ssq[j], red);
        if (tid == 0) {
            g_part2[j * NBLK2 + blockIdx.x]       = s.x;
            g_part2[(3 + j) * NBLK2 + blockIdx.x] = s.y;
        }
    }
    if (tid == 0) {
        __threadfence();
        s_last = (atomicAdd(&g_cnt2, 1u) == NBLK2 - 1);
    }
    __syncthreads();
    if (s_last) {
        finalize_bn(g_part2, 6, 3, 12, g2, b2, tot);
        if (tid == 0) g_cnt2 = 0;
    }
}

// ---------------- F3: bn2+lrelu -> a3 + fused BN3 stats ----------------
__global__ void __launch_bounds__(256) f3_kernel(const float* __restrict__ W3,
                                                 const float* __restrict__ g3,
                                                 const float* __restrict__ b3) {
    __shared__ float sW[3];
    __shared__ float sb[6];
    __shared__ float2 red[8];
    __shared__ float tot[12];
    __shared__ bool s_last;
    int tid = threadIdx.x;
    if (tid < 3) sW[tid] = W3[tid];
    if (tid < 6) sb[tid] = g_bn[12 + tid];
    __syncthreads();

    float sum = 0.f, ssq = 0.f;

    #pragma unroll
    for (int c = 0; c < 8; c++) {
        int e = blockIdx.x * EPB + c * 256 + tid;
        float s = 0.f;
        #pragma unroll
        for (int j = 0; j < 3; j++) {
            float a = g_a2[(size_t)j * E_TOT + e];
            float y = lrelu(fmaf(a, sb[j], sb[3 + j]));
            s = fmaf(sW[j], y, s);
        }
        g_a3[e] = s;
        sum += s;
        ssq = fmaf(s, s, ssq);
    }

    float2 t = blockReduceSum2(sum, ssq, red);
    if (tid == 0) {
        g_part3[blockIdx.x]         = t.x;
        g_part3[NBLK2 + blockIdx.x] = t.y;
    }
    if (tid == 0) {
        __threadfence();
        s_last = (atomicAdd(&g_cnt3, 1u) == NBLK2 - 1);
    }
    __syncthreads();
    if (s_last) {
        finalize_bn(g_part3, 2, 1, 18, g3, b3, tot);
        if (tid == 0) g_cnt3 = 0;
    }
}

// ---------------- F4: bn3+lrelu -> softmax -> gather -> out ----------------
__global__ void f4_kernel(float* __restrict__ out) {
    int gw = (blockIdx.x * blockDim.x + threadIdx.x) >> 5;  // global warp = point id
    int lane = threadIdx.x & 31;
    int b = gw >> 12, n = gw & (NN - 1);
    int base = gw * KK;

    float sc = g_bn[18], sh = g_bn[19];
    float logit = -FLT_MAX;
    int nb = 0;
    if (lane < KK) {
        float a = g_a3[base + lane];
        logit = lrelu(fmaf(a, sc, sh));
        nb = g_idx[base + lane];
    }
    float mx = logit;
    #pragma unroll
    for (int o = 16; o; o >>= 1) mx = fmaxf(mx, __shfl_xor_sync(0xffffffffu, mx, o));
    float ex = (lane < KK) ? expf(logit - mx) : 0.f;
    float s = ex;
    #pragma unroll
    for (int o = 16; o; o >>= 1) s += __shfl_xor_sync(0xffffffffu, s, o);
    float att = ex / s;

    const float* xTb = g_xT + (size_t)b * NN * CC;
    float acc0 = 0.f, acc1 = 0.f;
    #pragma unroll
    for (int kk = 0; kk < KK; kk++) {
        int   t = __shfl_sync(0xffffffffu, nb, kk);
        float a = __shfl_sync(0xffffffffu, att, kk);
        float2 v = *(const float2*)(xTb + (size_t)t * CC + lane * 2);
        acc0 = fmaf(a, v.x, acc0);
        acc1 = fmaf(a, v.y, acc1);
    }
    float2 c = *(const float2*)(xTb + (size_t)n * CC + lane * 2);
    float* ob = out + (size_t)b * CC * NN;
    ob[(size_t)(2 * lane)     * NN + n] = c.x + acc0;
    ob[(size_t)(2 * lane + 1) * NN + n] = c.y + acc1;
}

// ---------------- launch ----------------
extern "C" void kernel_launch(void* const* d_in, const int* in_sizes, int n_in,
                              void* d_out, int out_size) {
    const float* x_loc = (const float*)d_in[0];
    const float* x     = (const float*)d_in[1];
    const float* W1    = (const float*)d_in[2];
    const float* g1    = (const float*)d_in[3];
    const float* b1    = (const float*)d_in[4];
    const float* W2    = (const float*)d_in[5];
    const float* g2    = (const float*)d_in[6];
    const float* b2    = (const float*)d_in[7];
    const float* W3    = (const float*)d_in[8];
    const float* g3    = (const float*)d_in[9];
    const float* b3    = (const float*)d_in[10];
    float* out = (float*)d_out;

    transpose_kernel<<<dim3(NN / 32, CC / 32, BB), dim3(32, 8)>>>(x);
    knn_kernel<<<dim3(NN / 8, BB), 256>>>(x_loc);
    f1_kernel<<<NBLK2, 256>>>(x_loc, W1, g1, b1);
    f2_kernel<<<NBLK2, 256>>>(W2, g2, b2);
    f3_kernel<<<NBLK2, 256>>>(W3, g3, b3);
    f4_kernel<<<(BB * NN) / 8, 256>>>(out);
}

// round 11
// speedup vs baseline: 3.5893x; 1.0460x over previous
#include <cuda_runtime.h>
#include <cuda_bf16.h>
#include <float.h>
#include <math.h>

// Problem constants
#define BB 8
#define NN 4096
#define CC 64
#define KK 30
#define E_TOT (BB*NN*KK)          // 983040
#define EPB   2048                // elements per block in F kernels
#define NBLK2 (E_TOT/EPB)         // 480

// ---------------- scratch (device globals; no runtime allocation) ----------------
__device__ int   g_idx[E_TOT];                 // neighbor indices [B,N,K]
__device__ float g_h1[6*(size_t)E_TOT];        // layer1 pre-activations, SoA
__device__ float g_a2[3*(size_t)E_TOT];        // layer2 pre-activations, SoA
__device__ float g_a3[E_TOT];                  // layer3 pre-activations
__device__ float g_xT[(size_t)BB*NN*CC];       // x transposed to [B,N,C]
// partials transposed: [stat][block]
__device__ float g_part1[12*NBLK2];
__device__ float g_part2[6*NBLK2];
__device__ float g_part3[2*NBLK2];
__device__ float g_bn[20];  // [0:6) sc1 [6:12) sh1 [12:15) sc2 [15:18) sh2 [18] sc3 [19] sh3
__device__ unsigned g_cnt1 = 0, g_cnt2 = 0, g_cnt3 = 0;

// ---------------- helpers ----------------
__device__ __forceinline__ float2 blockReduceSum2(float a, float b, float2* sh) {
    #pragma unroll
    for (int o = 16; o; o >>= 1) {
        a += __shfl_down_sync(0xffffffffu, a, o);
        b += __shfl_down_sync(0xffffffffu, b, o);
    }
    int w = threadIdx.x >> 5;
    if ((threadIdx.x & 31) == 0) sh[w] = make_float2(a, b);
    __syncthreads();
    float2 r = make_float2(0.f, 0.f);
    if (w == 0) {
        if (threadIdx.x < 8) r = sh[threadIdx.x];
        #pragma unroll
        for (int o = 4; o; o >>= 1) {
            r.x += __shfl_down_sync(0xffffffffu, r.x, o);
            r.y += __shfl_down_sync(0xffffffffu, r.y, o);
        }
    }
    __syncthreads();
    return r;  // valid in thread 0
}

__device__ __forceinline__ float lrelu(float x) { return x > 0.f ? x : 0.2f * x; }

// Last-block finalize: reduce `nstat` partial rows of length NBLK2 (fixed order,
// deterministic), compute BN scale/shift for `nch` channels into g_bn[off..].
__device__ __forceinline__ void finalize_bn(const float* part, int nstat, int nch, int off,
                                            const float* gamma, const float* beta,
                                            float* tot /* shared[12] */) {
    __threadfence();
    int w = threadIdx.x >> 5, lane = threadIdx.x & 31;
    for (int st = w; st < nstat; st += 8) {
        const float* p = part + (size_t)st * NBLK2;
        float s = 0.f;
        for (int i = lane; i < NBLK2; i += 32) s += p[i];
        #pragma unroll
        for (int o = 16; o; o >>= 1) s += __shfl_down_sync(0xffffffffu, s, o);
        if (lane == 0) tot[st] = s;
    }
    __syncthreads();
    if (threadIdx.x < nch) {
        float inv = 1.f / (float)E_TOT;
        float mu  = tot[threadIdx.x] * inv;
        float var = tot[nch + threadIdx.x] * inv - mu * mu;
        float sc  = gamma[threadIdx.x] * rsqrtf(var + 1e-5f);
        g_bn[off + threadIdx.x] = sc;
        g_bn[off + nch + threadIdx.x] = beta[threadIdx.x] - mu * sc;
    }
}

// ---------------- transpose x: [B,C,N] -> [B,N,C] ----------------
__global__ void transpose_kernel(const float* __restrict__ x) {
    __shared__ float tile[32][33];
    int b = blockIdx.z;
    int c0 = blockIdx.y * 32, n0 = blockIdx.x * 32;
    const float* xb = x + (size_t)b * CC * NN;
    #pragma unroll
    for (int i = threadIdx.y; i < 32; i += 8)
        tile[i][threadIdx.x] = xb[(size_t)(c0 + i) * NN + n0 + threadIdx.x];
    __syncthreads();
    float* xt = g_xT + (size_t)b * NN * CC;
    #pragma unroll
    for (int i = threadIdx.y; i < 32; i += 8)
        xt[(size_t)(n0 + i) * CC + c0 + threadIdx.x] = tile[threadIdx.x][i];
}

// ---------------- kNN: one warp per query row, register 4-list + REDUX rounds ----------------
// Key = (float_bits(d2) << 32) | idx  — d2 >= 0 so float bits are order-monotone,
// idx in low bits makes keys unique => exact tie-break (lowest index) and exact
// exclusion on refill. Warp-min per round via 2x redux.sync.umin (lexicographic
// (d2bits, idx) == u64 order).
__global__ void __launch_bounds__(256) knn_kernel(const float* __restrict__ xloc) {
    const unsigned FULL = 0xffffffffu;
    const unsigned long long KMAX = 0xFFFFFFFFFFFFFFFFull;
    int b = blockIdx.y;
    int warp = threadIdx.x >> 5, lane = threadIdx.x & 31;
    int n = blockIdx.x * 8 + warp;

    const float* px = xloc + (size_t)b * 3 * NN;
    const float* py = px + NN;
    const float* pz = px + 2 * NN;
    const float4* px4 = (const float4*)px;
    const float4* py4 = (const float4*)py;
    const float4* pz4 = (const float4*)pz;
    float cx = __ldg(px + n), cy = __ldg(py + n), cz = __ldg(pz + n);

    // sorted ascending 4-list in registers
    unsigned long long k0 = KMAX, k1 = KMAX, k2 = KMAX, k3 = KMAX;

    #pragma unroll 2
    for (int i = 0; i < 32; i++) {
        int base = i * 32 + lane;
        float4 X = __ldg(px4 + base);
        float4 Y = __ldg(py4 + base);
        float4 Z = __ldg(pz4 + base);
        #pragma unroll
        for (int j = 0; j < 4; j++) {
            float dx = ((const float*)&X)[j] - cx;
            float dy = ((const float*)&Y)[j] - cy;
            float dz = ((const float*)&Z)[j] - cz;
            float d2 = fmaf(dz, dz, fmaf(dy, dy, dx * dx));
            unsigned d2b = __float_as_uint(d2);
            // fast reject: if d2bits > hi(k3), key >= k3 surely (never skips a qualifier)
            if (d2b <= (unsigned)(k3 >> 32)) {
                unsigned long long key =
                    ((unsigned long long)d2b << 32) | (unsigned)(base * 4 + j);
                if (key < k3) {
                    if (key < k2) {
                        k3 = k2;
                        if (key < k1) { k2 = k1; if (key < k0) { k1 = k0; k0 = key; } else k1 = key; }
                        else k2 = key;
                    } else k3 = key;
                }
            }
        }
    }

    unsigned long long lastpop = 0;
    int outbase = (b * NN + n) * KK;

    for (int it = 0; it < KK; it++) {
        // warp-wide u64 min of heads via 2x 32-bit redux (lexicographic)
        unsigned hb = (unsigned)(k0 >> 32);
        unsigned minhb = __reduce_min_sync(FULL, hb);
        unsigned myidx = (hb == minhb) ? (unsigned)k0 : 0xFFFFFFFFu;
        unsigned widx = __reduce_min_sync(FULL, myidx);
        if (lane == 0) g_idx[outbase + it] = (int)widx;
        // exactly one lane holds the global min key; it pops
        if (hb == minhb && (unsigned)k0 == widx) {
            lastpop = k0;
            k0 = k1; k1 = k2; k2 = k3; k3 = KMAX;
            if (k0 == KMAX) {
                // refill: rescan my candidates, keep 4 smallest keys > lastpop
                for (int i = 0; i < 32; i++) {
                    int base = i * 32 + lane;
                    float4 X = __ldg(px4 + base);
                    float4 Y = __ldg(py4 + base);
                    float4 Z = __ldg(pz4 + base);
                    #pragma unroll
                    for (int j = 0; j < 4; j++) {
                        float dx = ((const float*)&X)[j] - cx;
                        float dy = ((const float*)&Y)[j] - cy;
                        float dz = ((const float*)&Z)[j] - cz;
                        float d2 = fmaf(dz, dz, fmaf(dy, dy, dx * dx));
                        unsigned long long key =
                            ((unsigned long long)__float_as_uint(d2) << 32) | (unsigned)(base * 4 + j);
                        if (key > lastpop && key < k3) {
                            if (key < k2) {
                                k3 = k2;
                                if (key < k1) { k2 = k1; if (key < k0) { k1 = k0; k0 = key; } else k1 = key; }
                                else k2 = key;
                            } else k3 = key;
                        }
                    }
                }
            }
        }
    }
}

// ---------------- F1: spherical features -> h1 + fused BN1 stats ----------------
__global__ void __launch_bounds__(256) f1_kernel(const float* __restrict__ xloc,
                                                 const float* __restrict__ W1,
                                                 const float* __restrict__ g1,
                                                 const float* __restrict__ b1) {
    __shared__ float sW[36];
    __shared__ float2 red[8];
    __shared__ float tot[12];
    __shared__ bool s_last;
    int tid = threadIdx.x;
    if (tid < 36) sW[tid] = W1[tid];
    __syncthreads();

    float sum[6] = {0,0,0,0,0,0}, ssq[6] = {0,0,0,0,0,0};

    #pragma unroll
    for (int c = 0; c < 2; c++) {
        int e0 = blockIdx.x * EPB + c * 1024 + tid * 4;  // 4 consecutive elements
        int4 idx4 = *(const int4*)(g_idx + e0);
        float h4[6][4];
        #pragma unroll
        for (int v = 0; v < 4; v++) {
            int e = e0 + v;
            int b = e / (NN * KK);
            int rem = e - b * (NN * KK);
            int n = rem / KK;
            int idx = ((const int*)&idx4)[v];
            const float* xb = xloc + (size_t)b * 3 * NN;
            float cx = __ldg(xb + n), cy = __ldg(xb + NN + n), cz = __ldg(xb + 2*NN + n);
            float xr = __ldg(xb + idx) - cx, yr = __ldg(xb + NN + idx) - cy, zr = __ldg(xb + 2*NN + idx) - cz;

            float sxy2 = fmaf(yr, yr, xr * xr);
            float r2   = fmaf(zr, zr, sxy2);
            float rho  = sqrtf(fmaxf(r2, 1e-20f));
            float sxy  = sqrtf(fmaxf(sxy2, 1e-20f));
            bool deg_r = r2 < 1e-20f;
            bool deg_p = sxy2 < 1e-20f;
            float theta = atan2f(deg_r ? 0.f : zr, deg_r ? 1.f : sxy);
            float phi   = atan2f(deg_p ? 0.f : yr, deg_p ? 1.f : xr);
            float mean  = (rho + theta + phi) * (1.f / 3.f);
            float f[6] = { rho, theta, phi, rho - mean, theta - mean, phi - mean };

            #pragma unroll
            for (int j = 0; j < 6; j++) {
                float a = 0.f;
                #pragma unroll
                for (int i = 0; i < 6; i++) a = fmaf(sW[j * 6 + i], f[i], a);
                h4[j][v] = a;
                sum[j] += a;
                ssq[j] = fmaf(a, a, ssq[j]);
            }
        }
        #pragma unroll
        for (int j = 0; j < 6; j++)
            *(float4*)(g_h1 + (size_t)j * E_TOT + e0) =
                make_float4(h4[j][0], h4[j][1], h4[j][2], h4[j][3]);
    }

    #pragma unroll
    for (int j = 0; j < 6; j++) {
        float2 s = blockReduceSum2(sum[j], ssq[j], red);
        if (tid == 0) {
            g_part1[j * NBLK2 + blockIdx.x]       = s.x;
            g_part1[(6 + j) * NBLK2 + blockIdx.x] = s.y;
        }
    }
    if (tid == 0) {
        __threadfence();
        s_last = (atomicAdd(&g_cnt1, 1u) == NBLK2 - 1);
    }
    __syncthreads();
    if (s_last) {
        finalize_bn(g_part1, 12, 6, 0, g1, b1, tot);
        if (tid == 0) g_cnt1 = 0;
    }
}

// ---------------- F2: bn1+lrelu -> a2 + fused BN2 stats ----------------
__global__ void __launch_bounds__(256) f2_kernel(const float* __restrict__ W2,
                                                 const float* __restrict__ g2,
                                                 const float* __restrict__ b2) {
    __shared__ float sW[18];
    __shared__ float sb[12];
    __shared__ float2 red[8];
    __shared__ float tot[12];
    __shared__ bool s_last;
    int tid = threadIdx.x;
    if (tid < 18) sW[tid] = W2[tid];
    if (tid < 12) sb[tid] = g_bn[tid];
    __syncthreads();

    float sum[3] = {0,0,0}, ssq[3] = {0,0,0};

    #pragma unroll
    for (int c = 0; c < 2; c++) {
        int e0 = blockIdx.x * EPB + c * 1024 + tid * 4;
        float4 h4[6];
        #pragma unroll
        for (int j = 0; j < 6; j++)
            h4[j] = *(const float4*)(g_h1 + (size_t)j * E_TOT + e0);
        float4 a4[3];
        #pragma unroll
        for (int v = 0; v < 4; v++) {
            float y[6];
            #pragma unroll
            for (int j = 0; j < 6; j++)
                y[j] = lrelu(fmaf(((const float*)&h4[j])[v], sb[j], sb[6 + j]));
            #pragma unroll
            for (int j = 0; j < 3; j++) {
                float s = 0.f;
                #pragma unroll
                for (int i = 0; i < 6; i++) s = fmaf(sW[j * 6 + i], y[i], s);
                ((float*)&a4[j])[v] = s;
                sum[j] += s;
                ssq[j] = fmaf(s, s, ssq[j]);
            }
        }
        #pragma unroll
        for (int j = 0; j < 3; j++)
            *(float4*)(g_a2 + (size_t)j * E_TOT + e0) = a4[j];
    }

    #pragma unroll
    for (int j = 0; j < 3; j++) {
        float2 s = blockReduceSum2(sum[j], ssq[j], red);
        if (tid == 0) {
            g_part2[j * NBLK2 + blockIdx.x]       = s.x;
            g_part2[(3 + j) * NBLK2 + blockIdx.x] = s.y;
        }
    }
    if (tid == 0) {
        __threadfence();
        s_last = (atomicAdd(&g_cnt2, 1u) == NBLK2 - 1);
    }
    __syncthreads();
    if (s_last) {
        finalize_bn(g_part2, 6, 3, 12, g2, b2, tot);
        if (tid == 0) g_cnt2 = 0;
    }
}

// ---------------- F3: bn2+lrelu -> a3 + fused BN3 stats ----------------
__global__ void __launch_bounds__(256) f3_kernel(const float* __restrict__ W3,
                                                 const float* __restrict__ g3,
                                                 const float* __restrict__ b3) {
    __shared__ float sW[3];
    __shared__ float sb[6];
    __shared__ float2 red[8];
    __shared__ float tot[12];
    __shared__ bool s_last;
    int tid = threadIdx.x;
    if (tid < 3) sW[tid] = W3[tid];
    if (tid < 6) sb[tid] = g_bn[12 + tid];
    __syncthreads();

    float sum = 0.f, ssq = 0.f;

    #pragma unroll
    for (int c = 0; c < 2; c++) {
        int e0 = blockIdx.x * EPB + c * 1024 + tid * 4;
        float4 a4[3];
        #pragma unroll
        for (int j = 0; j < 3; j++)
            a4[j] = *(const float4*)(g_a2 + (size_t)j * E_TOT + e0);
        float4 s4;
        #pragma unroll
        for (int v = 0; v < 4; v++) {
            float s = 0.f;
            #pragma unroll
            for (int j = 0; j < 3; j++) {
                float y = lrelu(fmaf(((const float*)&a4[j])[v], sb[j], sb[3 + j]));
                s = fmaf(sW[j], y, s);
            }
            ((float*)&s4)[v] = s;
            sum += s;
            ssq = fmaf(s, s, ssq);
        }
        *(float4*)(g_a3 + e0) = s4;
    }

    float2 t = blockReduceSum2(sum, ssq, red);
    if (tid == 0) {
        g_part3[blockIdx.x]         = t.x;
        g_part3[NBLK2 + blockIdx.x] = t.y;
    }
    if (tid == 0) {
        __threadfence();
        s_last = (atomicAdd(&g_cnt3, 1u) == NBLK2 - 1);
    }
    __syncthreads();
    if (s_last) {
        finalize_bn(g_part3, 2, 1, 18, g3, b3, tot);
        if (tid == 0) g_cnt3 = 0;
    }
}

// ---------------- F4: bn3+lrelu -> softmax -> gather -> out ----------------
__global__ void f4_kernel(float* __restrict__ out) {
    int gw = (blockIdx.x * blockDim.x + threadIdx.x) >> 5;  // global warp = point id
    int lane = threadIdx.x & 31;
    int b = gw >> 12, n = gw & (NN - 1);
    int base = gw * KK;

    float sc = g_bn[18], sh = g_bn[19];
    float logit = -FLT_MAX;
    int nb = 0;
    if (lane < KK) {
        float a = g_a3[base + lane];
        logit = lrelu(fmaf(a, sc, sh));
        nb = g_idx[base + lane];
    }
    float mx = logit;
    #pragma unroll
    for (int o = 16; o; o >>= 1) mx = fmaxf(mx, __shfl_xor_sync(0xffffffffu, mx, o));
    float ex = (lane < KK) ? expf(logit - mx) : 0.f;
    float s = ex;
    #pragma unroll
    for (int o = 16; o; o >>= 1) s += __shfl_xor_sync(0xffffffffu, s, o);
    float att = ex / s;

    const float* xTb = g_xT + (size_t)b * NN * CC;
    float acc0 = 0.f, acc1 = 0.f;
    #pragma unroll
    for (int kk = 0; kk < KK; kk++) {
        int   t = __shfl_sync(0xffffffffu, nb, kk);
        float a = __shfl_sync(0xffffffffu, att, kk);
        float2 v = *(const float2*)(xTb + (size_t)t * CC + lane * 2);
        acc0 = fmaf(a, v.x, acc0);
        acc1 = fmaf(a, v.y, acc1);
    }
    float2 c = *(const float2*)(xTb + (size_t)n * CC + lane * 2);
    float* ob = out + (size_t)b * CC * NN;
    ob[(size_t)(2 * lane)     * NN + n] = c.x + acc0;
    ob[(size_t)(2 * lane + 1) * NN + n] = c.y + acc1;
}

// ---------------- launch ----------------
extern "C" void kernel_launch(void* const* d_in, const int* in_sizes, int n_in,
                              void* d_out, int out_size) {
    const float* x_loc = (const float*)d_in[0];
    const float* x     = (const float*)d_in[1];
    const float* W1    = (const float*)d_in[2];
    const float* g1    = (const float*)d_in[3];
    const float* b1    = (const float*)d_in[4];
    const float* W2    = (const float*)d_in[5];
    const float* g2    = (const float*)d_in[6];
    const float* b2    = (const float*)d_in[7];
    const float* W3    = (const float*)d_in[8];
    const float* g3    = (const float*)d_in[9];
    const float* b3    = (const float*)d_in[10];
    float* out = (float*)d_out;

    transpose_kernel<<<dim3(NN / 32, CC / 32, BB), dim3(32, 8)>>>(x);
    knn_kernel<<<dim3(NN / 8, BB), 256>>>(x_loc);
    f1_kernel<<<NBLK2, 256>>>(x_loc, W1, g1, b1);
    f2_kernel<<<NBLK2, 256>>>(W2, g2, b2);
    f3_kernel<<<NBLK2, 256>>>(W3, g3, b3);
    f4_kernel<<<(BB * NN) / 8, 256>>>(out);
}